// round 3
// baseline (speedup 1.0000x reference)
#include <cuda_runtime.h>
#include <cuda_bf16.h>
#include <math.h>

#define NN 20000
#define HID 128

// ---------------- device scratch (no allocations allowed) ----------------
__device__ float g_h[NN * HID];      // h
__device__ float g_m[NN * HID];      // h0 temp, then per-layer m
__device__ float g_skip[NN * HID];   // x_skip
__device__ float g_agg[NN * HID];    // x_agg
__device__ float g_inv1[NN];
__device__ float g_inv2[NN];
__device__ float g_s1[NN];           // deg temp, then gamma sums (1-hop)
__device__ float g_s2[NN];           // deg temp, then gamma sums (2-hop)

// ---------------- generic helpers ----------------
__global__ void zero_kernel(float* __restrict__ p, int n) {
    int i = blockIdx.x * blockDim.x + threadIdx.x;
    if (i < n) p[i] = 0.0f;
}

__global__ void count_deg(const int* __restrict__ row, float* __restrict__ deg, int E) {
    int e = blockIdx.x * blockDim.x + threadIdx.x;
    if (e < E) atomicAdd(&deg[row[e]], 1.0f);
}

__global__ void invert_deg(const float* __restrict__ deg, float* __restrict__ inv, int n) {
    int i = blockIdx.x * blockDim.x + threadIdx.x;
    if (i < n) inv[i] = 1.0f / (deg[i] + 1e-10f);
}

// ---------------- GEMM: C[N,128] = A[N,128] @ W[128,128] ----------------
__global__ __launch_bounds__(256) void gemm128(const float* __restrict__ A,
                                               const float* __restrict__ W,
                                               float* __restrict__ C, int N) {
    __shared__ float As[128][33];   // pad to kill bank conflicts
    __shared__ float Ws[32][128];
    const int tid = threadIdx.x;
    const int tx = tid & 15;        // 0..15 -> output col group
    const int ty = tid >> 4;        // 0..15 -> output row group
    const int rowBase = blockIdx.x * 128;

    float acc[8][8];
#pragma unroll
    for (int i = 0; i < 8; i++)
#pragma unroll
        for (int j = 0; j < 8; j++) acc[i][j] = 0.0f;

    for (int k0 = 0; k0 < 128; k0 += 32) {
        // load A tile 128x32 (1024 float4s, 4 per thread)
#pragma unroll
        for (int t = 0; t < 4; t++) {
            int idx4 = tid + t * 256;
            int r = idx4 >> 3;
            int kk = (idx4 & 7) * 4;
            float4 v = make_float4(0.f, 0.f, 0.f, 0.f);
            if (rowBase + r < N)
                v = *reinterpret_cast<const float4*>(&A[(size_t)(rowBase + r) * HID + k0 + kk]);
            As[r][kk + 0] = v.x; As[r][kk + 1] = v.y;
            As[r][kk + 2] = v.z; As[r][kk + 3] = v.w;
        }
        // load W tile 32x128
#pragma unroll
        for (int t = 0; t < 4; t++) {
            int idx4 = tid + t * 256;
            int kk = idx4 >> 5;
            int c = (idx4 & 31) * 4;
            *reinterpret_cast<float4*>(&Ws[kk][c]) =
                *reinterpret_cast<const float4*>(&W[(size_t)(k0 + kk) * HID + c]);
        }
        __syncthreads();
#pragma unroll
        for (int kk = 0; kk < 32; kk++) {
            float a[8], w[8];
#pragma unroll
            for (int i = 0; i < 8; i++) a[i] = As[ty * 8 + i][kk];
#pragma unroll
            for (int j = 0; j < 8; j++) w[j] = Ws[kk][tx + 16 * j];
#pragma unroll
            for (int i = 0; i < 8; i++)
#pragma unroll
                for (int j = 0; j < 8; j++) acc[i][j] += a[i] * w[j];
        }
        __syncthreads();
    }
#pragma unroll
    for (int i = 0; i < 8; i++) {
        int r = rowBase + ty * 8 + i;
        if (r < N) {
#pragma unroll
            for (int j = 0; j < 8; j++)
                C[(size_t)r * HID + tx + 16 * j] = acc[i][j];
        }
    }
}

// ---------------- scatter: agg[col[e]] += m[row[e]]  (vector red) ----------------
__global__ void scatter_add(const float* __restrict__ m, const int* __restrict__ row,
                            const int* __restrict__ col, float* __restrict__ agg, int E) {
    int w = (blockIdx.x * blockDim.x + threadIdx.x) >> 5;
    if (w >= E) return;
    int lane = threadIdx.x & 31;
    int r = row[w];
    int c = col[w];
    float4 v = *reinterpret_cast<const float4*>(&m[(size_t)r * HID + lane * 4]);
    float* dst = &agg[(size_t)c * HID + lane * 4];
    asm volatile("red.global.add.v4.f32 [%0], {%1, %2, %3, %4};"
                 :: "l"(dst), "f"(v.x), "f"(v.y), "f"(v.z), "f"(v.w) : "memory");
}

// ---------------- bias + relu ----------------
__global__ void bias_relu(float* __restrict__ agg, const float* __restrict__ b) {
    int i = blockIdx.x * blockDim.x + threadIdx.x;
    if (i < NN * HID) {
        float v = agg[i] + b[i & (HID - 1)];
        agg[i] = v > 0.0f ? v : 0.0f;
    }
}

// ---------------- gamma edge sums: gsum[row] += ||agg[row]-agg[col]||^2 ----------------
__global__ void gamma_edges(const float* __restrict__ agg, const int* __restrict__ row,
                            const int* __restrict__ col, float* __restrict__ gsum, int E) {
    int w = (blockIdx.x * blockDim.x + threadIdx.x) >> 5;
    if (w >= E) return;
    int lane = threadIdx.x & 31;
    int r = row[w];
    int c = col[w];
    float4 a = *reinterpret_cast<const float4*>(&agg[(size_t)r * HID + lane * 4]);
    float4 b = *reinterpret_cast<const float4*>(&agg[(size_t)c * HID + lane * 4]);
    float dx = a.x - b.x, dy = a.y - b.y, dz = a.z - b.z, dw = a.w - b.w;
    float s = dx * dx + dy * dy + dz * dz + dw * dw;
#pragma unroll
    for (int off = 16; off; off >>= 1) s += __shfl_xor_sync(0xffffffffu, s, off);
    if (lane == 0) atomicAdd(&gsum[r], s);
}

// ---------------- h update ----------------
__global__ void update_h(float* __restrict__ h, const float* __restrict__ agg,
                         const float* __restrict__ skip, const float* __restrict__ s1,
                         const float* __restrict__ s2, const float* __restrict__ inv1,
                         const float* __restrict__ inv2) {
    int i = blockIdx.x * blockDim.x + threadIdx.x;   // over NN*32 float4s
    if (i >= NN * (HID / 4)) return;
    int node = i >> 5;
    float g1 = tanhf(s1[node] * inv1[node]);
    float g2 = tanhf(s2[node] * inv2[node]);
    float invd = 1.0f / (1.0f + g1 + g2);
    float4 hv = reinterpret_cast<float4*>(h)[i];
    float4 av = reinterpret_cast<const float4*>(agg)[i];
    float4 sv = reinterpret_cast<const float4*>(skip)[i];
    hv.x = (hv.x + g1 * av.x + g2 * sv.x) * invd;
    hv.y = (hv.y + g1 * av.y + g2 * sv.y) * invd;
    hv.z = (hv.z + g1 * av.z + g2 * sv.z) * invd;
    hv.w = (hv.w + g1 * av.w + g2 * sv.w) * invd;
    reinterpret_cast<float4*>(h)[i] = hv;
}

// ---------------- final GEMM: out[N,40] = h @ fc_W + fc_b ----------------
__global__ void gemm_out(const float* __restrict__ A, const float* __restrict__ W,
                         const float* __restrict__ bias, float* __restrict__ C, int N) {
    __shared__ float Ws[HID * 40];
    __shared__ float bs[40];
    __shared__ float As[6][HID];
    int tid = threadIdx.y * 40 + threadIdx.x;   // 240 threads
    for (int i = tid; i < HID * 40; i += 240) Ws[i] = W[i];
    if (tid < 40) bs[tid] = bias[tid];
    int rowBase = blockIdx.x * 6;
    for (int i = tid; i < 6 * HID; i += 240) {
        int rr = i >> 7, kk = i & (HID - 1);
        As[rr][kk] = (rowBase + rr < N) ? A[(size_t)(rowBase + rr) * HID + kk] : 0.0f;
    }
    __syncthreads();
    int row = rowBase + threadIdx.y;
    if (row >= N) return;
    float acc = bs[threadIdx.x];
#pragma unroll
    for (int k = 0; k < HID; k++) acc += As[threadIdx.y][k] * Ws[k * 40 + threadIdx.x];
    C[(size_t)row * 40 + threadIdx.x] = acc;
}

// ---------------- launcher ----------------
extern "C" void kernel_launch(void* const* d_in, const int* in_sizes, int n_in,
                              void* d_out, int out_size) {
    const float* x       = (const float*)d_in[0];
    const float* x0      = (const float*)d_in[1];
    const int*   ei      = (const int*)d_in[2];
    const int*   ei2     = (const int*)d_in[3];
    const float* in_W    = (const float*)d_in[4];
    const float* skip_W  = (const float*)d_in[5];
    const float* conv_W  = (const float*)d_in[6];
    const float* conv_b  = (const float*)d_in[7];
    const float* fc_W    = (const float*)d_in[8];
    const float* fc_b    = (const float*)d_in[9];
    float* out = (float*)d_out;

    const int E1 = in_sizes[2] / 2;
    const int E2 = in_sizes[3] / 2;
    const int* row1 = ei;
    const int* col1 = ei + E1;
    const int* row2 = ei2;
    const int* col2 = ei2 + E2;

    float *h, *m, *skip, *agg, *inv1, *inv2, *s1, *s2;
    cudaGetSymbolAddress((void**)&h,    g_h);
    cudaGetSymbolAddress((void**)&m,    g_m);
    cudaGetSymbolAddress((void**)&skip, g_skip);
    cudaGetSymbolAddress((void**)&agg,  g_agg);
    cudaGetSymbolAddress((void**)&inv1, g_inv1);
    cudaGetSymbolAddress((void**)&inv2, g_inv2);
    cudaGetSymbolAddress((void**)&s1,   g_s1);
    cudaGetSymbolAddress((void**)&s2,   g_s2);

    const int NTH = 256;
    const int gemmBlocks = (NN + 127) / 128;
    const int nodeGrid   = (NN + NTH - 1) / NTH;
    const int featGrid   = (NN * HID + NTH - 1) / NTH;
    const int vec4Grid   = (NN * (HID / 4) + NTH - 1) / NTH;

    // degrees -> inverse degrees (static per call)
    zero_kernel<<<nodeGrid, NTH>>>(s1, NN);
    zero_kernel<<<nodeGrid, NTH>>>(s2, NN);
    count_deg<<<(E1 + NTH - 1) / NTH, NTH>>>(row1, s1, E1);
    count_deg<<<(E2 + NTH - 1) / NTH, NTH>>>(row2, s2, E2);
    invert_deg<<<nodeGrid, NTH>>>(s1, inv1, NN);
    invert_deg<<<nodeGrid, NTH>>>(s2, inv2, NN);

    // input projections
    gemm128<<<gemmBlocks, NTH>>>(x, in_W, h, NN);      // h = x @ in_W
    gemm128<<<gemmBlocks, NTH>>>(x0, in_W, m, NN);     // h0 (temp in m)
    gemm128<<<gemmBlocks, NTH>>>(m, skip_W, skip, NN); // x_skip = h0 @ skip_W

    for (int l = 0; l < 2; l++) {
        gemm128<<<gemmBlocks, NTH>>>(h, conv_W + (size_t)l * HID * HID, m, NN);

        zero_kernel<<<featGrid, NTH>>>(agg, NN * HID);
        zero_kernel<<<nodeGrid, NTH>>>(s1, NN);
        zero_kernel<<<nodeGrid, NTH>>>(s2, NN);

        scatter_add<<<(int)(((size_t)E1 * 32 + NTH - 1) / NTH), NTH>>>(m, row1, col1, agg, E1);
        bias_relu<<<featGrid, NTH>>>(agg, conv_b + l * HID);

        gamma_edges<<<(int)(((size_t)E1 * 32 + NTH - 1) / NTH), NTH>>>(agg, row1, col1, s1, E1);
        gamma_edges<<<(int)(((size_t)E2 * 32 + NTH - 1) / NTH), NTH>>>(agg, row2, col2, s2, E2);

        update_h<<<vec4Grid, NTH>>>(h, agg, skip, s1, s2, inv1, inv2);
    }

    gemm_out<<<(NN + 5) / 6, dim3(40, 6)>>>(h, fc_W, fc_b, out, NN);
}

// round 4
// speedup vs baseline: 1.4639x; 1.4639x over previous
#include <cuda_runtime.h>
#include <cuda_bf16.h>
#include <math.h>

#define NN 20000
#define HID 128

// ---------------- single scratch buffer (contiguity matters) ----------------
#define OFF_H     0
#define OFF_M     2560000
#define OFF_SKIP  5120000
#define OFF_AGG   7680000
#define OFF_S1    10240000   // contiguous: agg | s1 | s2  (one zero pass)
#define OFF_S2    10260000
#define OFF_INV1  10280000   // contiguous: inv1 | inv2
#define OFF_INV2  10300000
#define SCRATCH_F 10320000
__device__ float g_scratch[SCRATCH_F];

// ---------------- helpers ----------------
__global__ void zero4_kernel(float4* __restrict__ p, int n4) {
    int i = blockIdx.x * blockDim.x + threadIdx.x;
    if (i < n4) p[i] = make_float4(0.f, 0.f, 0.f, 0.f);
}

// warp-aggregated degree count (big win on sorted row2)
__global__ void count_deg(const int* __restrict__ row, float* __restrict__ deg, int E) {
    int e = blockIdx.x * blockDim.x + threadIdx.x;
    if (e >= E) return;
    int r = row[e];
    unsigned m = __match_any_sync(__activemask(), r);
    int lane = threadIdx.x & 31;
    if (lane == (__ffs(m) - 1)) atomicAdd(&deg[r], (float)__popc(m));
}

__global__ void invert_deg2(const float* __restrict__ deg, float* __restrict__ inv, int n) {
    int i = blockIdx.x * blockDim.x + threadIdx.x;
    if (i < n) inv[i] = 1.0f / (deg[i] + 1e-10f);
}

__device__ __forceinline__ unsigned f2tf32(float x) {
    unsigned r;
    asm("cvt.rna.tf32.f32 %0, %1;" : "=r"(r) : "f"(x));
    return r;
}

__device__ __forceinline__ float warp_red(float s) {
#pragma unroll
    for (int off = 16; off; off >>= 1) s += __shfl_xor_sync(0xffffffffu, s, off);
    return s;
}

// ---------------- split-TF32 tensor GEMM: C[N,128] = A[N,128] @ W[128,128] ----------------
// Block: 256 threads (8 warps), tile M=128 x N=128, K-chunks of 16.
// A and W split into (hi, lo) tf32 on the fly in the smem-load path.
// D = Ah*Wh + Ah*Wl + Al*Wh  (Al*Wl ~ 2^-22 rel, dropped).
#define KCH 16
#define SPAD 136    // smem row stride (words): bank = (8k + m) % 32 -> conflict-free frag loads
__global__ __launch_bounds__(256) void gemm_tf32(const float* __restrict__ A,
                                                 const float* __restrict__ W,
                                                 float* __restrict__ C, int N) {
    __shared__ unsigned As_hi[KCH * SPAD], As_lo[KCH * SPAD];   // [k][m] transposed
    __shared__ unsigned Ws_hi[KCH * SPAD], Ws_lo[KCH * SPAD];   // [k][n]

    const int tid = threadIdx.x;
    const int lane = tid & 31;
    const int warp = tid >> 5;
    const int g = lane >> 2;       // groupID 0..7
    const int t = lane & 3;        // thread-in-group 0..3
    const int mbase = warp * 16;   // warp's row strip
    const int rowBase = blockIdx.x * 128;

    float acc[16][4];
#pragma unroll
    for (int n = 0; n < 16; n++)
#pragma unroll
        for (int j = 0; j < 4; j++) acc[n][j] = 0.0f;

    for (int k0 = 0; k0 < HID; k0 += KCH) {
        // load A tile: 128 rows x 16 k (lanes 0-3 cover one row -> 64B coalesced)
#pragma unroll
        for (int tt = 0; tt < 2; tt++) {
            int idx = tid + tt * 256;            // 0..511
            int r = idx >> 2;                    // 0..127
            int kq = (idx & 3) * 4;              // 0,4,8,12
            float4 v = make_float4(0.f, 0.f, 0.f, 0.f);
            if (rowBase + r < N)
                v = *reinterpret_cast<const float4*>(&A[(size_t)(rowBase + r) * HID + k0 + kq]);
            float f[4] = {v.x, v.y, v.z, v.w};
#pragma unroll
            for (int j = 0; j < 4; j++) {
                unsigned hi = f2tf32(f[j]);
                float lo = f[j] - __uint_as_float(hi);
                As_hi[(kq + j) * SPAD + r] = hi;
                As_lo[(kq + j) * SPAD + r] = f2tf32(lo);
            }
        }
        // load W tile: 16 k-rows x 128 n (each warp covers a full 512B row)
#pragma unroll
        for (int tt = 0; tt < 2; tt++) {
            int idx = tid + tt * 256;
            int kr = idx >> 5;                   // 0..15
            int nq = (idx & 31) * 4;
            float4 v = *reinterpret_cast<const float4*>(&W[(size_t)(k0 + kr) * HID + nq]);
            float f[4] = {v.x, v.y, v.z, v.w};
#pragma unroll
            for (int j = 0; j < 4; j++) {
                unsigned hi = f2tf32(f[j]);
                float lo = f[j] - __uint_as_float(hi);
                Ws_hi[kr * SPAD + nq + j] = hi;
                Ws_lo[kr * SPAD + nq + j] = f2tf32(lo);
            }
        }
        __syncthreads();

#pragma unroll
        for (int ks = 0; ks < KCH / 8; ks++) {
            int kb = ks * 8;
            unsigned ah[4], al[4];
            ah[0] = As_hi[(kb + t) * SPAD + mbase + g];
            ah[1] = As_hi[(kb + t) * SPAD + mbase + g + 8];
            ah[2] = As_hi[(kb + t + 4) * SPAD + mbase + g];
            ah[3] = As_hi[(kb + t + 4) * SPAD + mbase + g + 8];
            al[0] = As_lo[(kb + t) * SPAD + mbase + g];
            al[1] = As_lo[(kb + t) * SPAD + mbase + g + 8];
            al[2] = As_lo[(kb + t + 4) * SPAD + mbase + g];
            al[3] = As_lo[(kb + t + 4) * SPAD + mbase + g + 8];
#pragma unroll
            for (int nt = 0; nt < 16; nt++) {
                int nb = nt * 8;
                unsigned bh0 = Ws_hi[(kb + t) * SPAD + nb + g];
                unsigned bh1 = Ws_hi[(kb + t + 4) * SPAD + nb + g];
                unsigned bl0 = Ws_lo[(kb + t) * SPAD + nb + g];
                unsigned bl1 = Ws_lo[(kb + t + 4) * SPAD + nb + g];
                asm volatile("mma.sync.aligned.m16n8k8.row.col.f32.tf32.tf32.f32 "
                             "{%0,%1,%2,%3}, {%4,%5,%6,%7}, {%8,%9}, {%0,%1,%2,%3};"
                             : "+f"(acc[nt][0]), "+f"(acc[nt][1]), "+f"(acc[nt][2]), "+f"(acc[nt][3])
                             : "r"(ah[0]), "r"(ah[1]), "r"(ah[2]), "r"(ah[3]), "r"(bh0), "r"(bh1));
                asm volatile("mma.sync.aligned.m16n8k8.row.col.f32.tf32.tf32.f32 "
                             "{%0,%1,%2,%3}, {%4,%5,%6,%7}, {%8,%9}, {%0,%1,%2,%3};"
                             : "+f"(acc[nt][0]), "+f"(acc[nt][1]), "+f"(acc[nt][2]), "+f"(acc[nt][3])
                             : "r"(ah[0]), "r"(ah[1]), "r"(ah[2]), "r"(ah[3]), "r"(bl0), "r"(bl1));
                asm volatile("mma.sync.aligned.m16n8k8.row.col.f32.tf32.tf32.f32 "
                             "{%0,%1,%2,%3}, {%4,%5,%6,%7}, {%8,%9}, {%0,%1,%2,%3};"
                             : "+f"(acc[nt][0]), "+f"(acc[nt][1]), "+f"(acc[nt][2]), "+f"(acc[nt][3])
                             : "r"(al[0]), "r"(al[1]), "r"(al[2]), "r"(al[3]), "r"(bh0), "r"(bh1));
            }
        }
        __syncthreads();
    }

    // store: c0,c1 -> (row, 2t), (row, 2t+1); c2,c3 -> row+8
    int r0 = rowBase + mbase + g;
    int r1 = r0 + 8;
    if (r0 < N) {
#pragma unroll
        for (int nt = 0; nt < 16; nt++)
            *reinterpret_cast<float2*>(&C[(size_t)r0 * HID + nt * 8 + 2 * t]) =
                make_float2(acc[nt][0], acc[nt][1]);
    }
    if (r1 < N) {
#pragma unroll
        for (int nt = 0; nt < 16; nt++)
            *reinterpret_cast<float2*>(&C[(size_t)r1 * HID + nt * 8 + 2 * t]) =
                make_float2(acc[nt][2], acc[nt][3]);
    }
}

// ---------------- scatter: agg[col[e]] += m[row[e]]  (vector red) ----------------
__global__ void scatter_add(const float* __restrict__ m, const int* __restrict__ row,
                            const int* __restrict__ col, float* __restrict__ agg, int E) {
    int w = (blockIdx.x * blockDim.x + threadIdx.x) >> 5;
    if (w >= E) return;
    int lane = threadIdx.x & 31;
    int r = row[w];
    int c = col[w];
    float4 v = *reinterpret_cast<const float4*>(&m[(size_t)r * HID + lane * 4]);
    float* dst = &agg[(size_t)c * HID + lane * 4];
    asm volatile("red.global.add.v4.f32 [%0], {%1, %2, %3, %4};"
                 :: "l"(dst), "f"(v.x), "f"(v.y), "f"(v.z), "f"(v.w) : "memory");
}

// ---------------- bias + relu ----------------
__global__ void bias_relu(float* __restrict__ agg, const float* __restrict__ b) {
    int i = blockIdx.x * blockDim.x + threadIdx.x;
    if (i < NN * HID) {
        float v = agg[i] + b[i & (HID - 1)];
        agg[i] = v > 0.0f ? v : 0.0f;
    }
}

// ---------------- gamma, unsorted rows (1-hop): warp per edge ----------------
__global__ void gamma_edges(const float* __restrict__ agg, const int* __restrict__ row,
                            const int* __restrict__ col, float* __restrict__ gsum, int E) {
    int w = (blockIdx.x * blockDim.x + threadIdx.x) >> 5;
    if (w >= E) return;
    int lane = threadIdx.x & 31;
    int r = row[w];
    int c = col[w];
    float4 a = *reinterpret_cast<const float4*>(&agg[(size_t)r * HID + lane * 4]);
    float4 b = *reinterpret_cast<const float4*>(&agg[(size_t)c * HID + lane * 4]);
    float dx = a.x - b.x, dy = a.y - b.y, dz = a.z - b.z, dw = a.w - b.w;
    float s = warp_red(fmaf(dx, dx, fmaf(dy, dy, fmaf(dz, dz, dw * dw))));
    if (lane == 0) atomicAdd(&gsum[r], s);
}

// ---------------- gamma, SORTED rows (2-hop): warp per 64-edge chunk, cache a_row ----------------
#define G2_CHUNK 64
__global__ void gamma_edges_sorted(const float* __restrict__ agg, const int* __restrict__ row,
                                   const int* __restrict__ col, float* __restrict__ gsum, int E) {
    int w = (blockIdx.x * blockDim.x + threadIdx.x) >> 5;
    int lane = threadIdx.x & 31;
    int base = w * G2_CHUNK;
    if (base >= E) return;
    int end = min(base + G2_CHUNK, E);

    int curR = row[base];
    float4 ar = *reinterpret_cast<const float4*>(&agg[(size_t)curR * HID + lane * 4]);
    float acc = 0.0f;
    for (int e = base; e < end; e++) {
        int r = row[e];                 // warp-uniform (broadcast)
        if (r != curR) {
            float s = warp_red(acc);
            if (lane == 0) atomicAdd(&gsum[curR], s);
            acc = 0.0f;
            curR = r;
            ar = *reinterpret_cast<const float4*>(&agg[(size_t)r * HID + lane * 4]);
        }
        int c = col[e];
        float4 ac = *reinterpret_cast<const float4*>(&agg[(size_t)c * HID + lane * 4]);
        float dx = ar.x - ac.x, dy = ar.y - ac.y, dz = ar.z - ac.z, dw = ar.w - ac.w;
        acc += fmaf(dx, dx, fmaf(dy, dy, fmaf(dz, dz, dw * dw)));
    }
    float s = warp_red(acc);
    if (lane == 0) atomicAdd(&gsum[curR], s);
}

// ---------------- h update ----------------
__global__ void update_h(float* __restrict__ h, const float* __restrict__ agg,
                         const float* __restrict__ skip, const float* __restrict__ s1,
                         const float* __restrict__ s2, const float* __restrict__ inv1,
                         const float* __restrict__ inv2) {
    int i = blockIdx.x * blockDim.x + threadIdx.x;   // over NN*32 float4s
    if (i >= NN * (HID / 4)) return;
    int node = i >> 5;
    float g1 = tanhf(s1[node] * inv1[node]);
    float g2 = tanhf(s2[node] * inv2[node]);
    float invd = 1.0f / (1.0f + g1 + g2);
    float4 hv = reinterpret_cast<float4*>(h)[i];
    float4 av = reinterpret_cast<const float4*>(agg)[i];
    float4 sv = reinterpret_cast<const float4*>(skip)[i];
    hv.x = (hv.x + g1 * av.x + g2 * sv.x) * invd;
    hv.y = (hv.y + g1 * av.y + g2 * sv.y) * invd;
    hv.z = (hv.z + g1 * av.z + g2 * sv.z) * invd;
    hv.w = (hv.w + g1 * av.w + g2 * sv.w) * invd;
    reinterpret_cast<float4*>(h)[i] = hv;
}

// ---------------- final GEMM: out[N,40] = h @ fc_W + fc_b ----------------
__global__ void gemm_out(const float* __restrict__ A, const float* __restrict__ W,
                         const float* __restrict__ bias, float* __restrict__ C, int N) {
    __shared__ float Ws[HID * 41];   // pad stride 41 -> conflict-free
    __shared__ float bs[40];
    __shared__ float As[6][HID];
    int tid = threadIdx.y * 40 + threadIdx.x;   // 240 threads
    for (int i = tid; i < HID * 40; i += 240) {
        int k = i / 40, n = i % 40;
        Ws[k * 41 + n] = W[i];
    }
    if (tid < 40) bs[tid] = bias[tid];
    int rowBase = blockIdx.x * 6;
    for (int i = tid; i < 6 * HID; i += 240) {
        int rr = i >> 7, kk = i & (HID - 1);
        As[rr][kk] = (rowBase + rr < N) ? A[(size_t)(rowBase + rr) * HID + kk] : 0.0f;
    }
    __syncthreads();
    int row = rowBase + threadIdx.y;
    if (row >= N) return;
    float acc = bs[threadIdx.x];
#pragma unroll
    for (int k = 0; k < HID; k++) acc = fmaf(As[threadIdx.y][k], Ws[k * 41 + threadIdx.x], acc);
    C[(size_t)row * 40 + threadIdx.x] = acc;
}

// ---------------- launcher ----------------
extern "C" void kernel_launch(void* const* d_in, const int* in_sizes, int n_in,
                              void* d_out, int out_size) {
    const float* x       = (const float*)d_in[0];
    const float* x0      = (const float*)d_in[1];
    const int*   ei      = (const int*)d_in[2];
    const int*   ei2     = (const int*)d_in[3];
    const float* in_W    = (const float*)d_in[4];
    const float* skip_W  = (const float*)d_in[5];
    const float* conv_W  = (const float*)d_in[6];
    const float* conv_b  = (const float*)d_in[7];
    const float* fc_W    = (const float*)d_in[8];
    const float* fc_b    = (const float*)d_in[9];
    float* out = (float*)d_out;

    const int E1 = in_sizes[2] / 2;
    const int E2 = in_sizes[3] / 2;
    const int* row1 = ei;
    const int* col1 = ei + E1;
    const int* row2 = ei2;
    const int* col2 = ei2 + E2;

    float* base;
    cudaGetSymbolAddress((void**)&base, g_scratch);
    float* h    = base + OFF_H;
    float* m    = base + OFF_M;
    float* skip = base + OFF_SKIP;
    float* agg  = base + OFF_AGG;
    float* s1   = base + OFF_S1;
    float* s2   = base + OFF_S2;
    float* inv1 = base + OFF_INV1;
    float* inv2 = base + OFF_INV2;

    const int NTH = 256;
    const int gemmBlocks = (NN + 127) / 128;
    const int vec4Grid   = (NN * (HID / 4) + NTH - 1) / NTH;
    const int featGrid   = (NN * HID + NTH - 1) / NTH;

    // degrees -> inverse degrees
    zero4_kernel<<<(2 * NN / 4 + NTH - 1) / NTH, NTH>>>((float4*)s1, 2 * NN / 4);
    count_deg<<<(E1 + NTH - 1) / NTH, NTH>>>(row1, s1, E1);
    count_deg<<<(E2 + NTH - 1) / NTH, NTH>>>(row2, s2, E2);
    invert_deg2<<<(2 * NN + NTH - 1) / NTH, NTH>>>(s1, inv1, 2 * NN);  // s1|s2 -> inv1|inv2

    // input projections (split-tf32 tensor GEMMs)
    gemm_tf32<<<gemmBlocks, NTH>>>(x, in_W, h, NN);      // h = x @ in_W
    gemm_tf32<<<gemmBlocks, NTH>>>(x0, in_W, m, NN);     // h0 (temp in m)
    gemm_tf32<<<gemmBlocks, NTH>>>(m, skip_W, skip, NN); // x_skip = h0 @ skip_W

    const int zeroLayerN4 = (NN * HID + 2 * NN) / 4;     // agg | s1 | s2 contiguous
    for (int l = 0; l < 2; l++) {
        gemm_tf32<<<gemmBlocks, NTH>>>(h, conv_W + (size_t)l * HID * HID, m, NN);

        zero4_kernel<<<(zeroLayerN4 + NTH - 1) / NTH, NTH>>>((float4*)agg, zeroLayerN4);

        scatter_add<<<(int)(((size_t)E1 * 32 + NTH - 1) / NTH), NTH>>>(m, row1, col1, agg, E1);
        bias_relu<<<featGrid, NTH>>>(agg, conv_b + l * HID);

        gamma_edges<<<(int)(((size_t)E1 * 32 + NTH - 1) / NTH), NTH>>>(agg, row1, col1, s1, E1);
        {
            int warps = (E2 + G2_CHUNK - 1) / G2_CHUNK;
            int blocks = (int)(((size_t)warps * 32 + NTH - 1) / NTH);
            gamma_edges_sorted<<<blocks, NTH>>>(agg, row2, col2, s2, E2);
        }

        update_h<<<vec4Grid, NTH>>>(h, agg, skip, s1, s2, inv1, inv2);
    }

    gemm_out<<<(NN + 5) / 6, dim3(40, 6)>>>(h, fc_W, fc_b, out, NN);
}

// round 6
// speedup vs baseline: 1.5889x; 1.0854x over previous
#include <cuda_runtime.h>
#include <cuda_bf16.h>
#include <math.h>

#define NN 20000
#define HID 128
#define GB 157          // GEMM blocks for 20000 rows @128/tile

// ---------------- single scratch buffer ----------------
#define OFF_H     0
#define OFF_M     2560000
#define OFF_SKIP  5120000
#define OFF_AGG   7680000
#define OFF_S1    10240000   // contiguous after agg: agg | s1 | s2
#define OFF_S2    10260000
#define OFF_DEG1  10280000   // contiguous: deg1 | deg2
#define OFF_DEG2  10300000
#define SCRATCH_F 10320000
__device__ float g_scratch[SCRATCH_F];

// ---------------- helpers ----------------
__global__ void zero4_kernel(float4* __restrict__ p, int n4) {
    int i = blockIdx.x * blockDim.x + threadIdx.x;
    if (i < n4) p[i] = make_float4(0.f, 0.f, 0.f, 0.f);
}

// agg <- broadcast bias ; s1|s2 <- 0   (agg|s1|s2 contiguous)
__global__ void init_agg(float4* __restrict__ agg4, const float4* __restrict__ bias4) {
    int i = blockIdx.x * blockDim.x + threadIdx.x;
    const int NA = NN * HID / 4;
    if (i < NA) agg4[i] = bias4[i & 31];
    else if (i < NA + 2 * NN / 4) agg4[i] = make_float4(0.f, 0.f, 0.f, 0.f);
}

// fused warp-aggregated degree count for both edge lists (deg2 = deg + NN)
__global__ void count_deg_both(const int* __restrict__ row1, int E1,
                               const int* __restrict__ row2, int E2,
                               float* __restrict__ deg) {
    int e = blockIdx.x * blockDim.x + threadIdx.x;
    if (e >= E1 + E2) return;
    int key = (e < E1) ? row1[e] : (NN + row2[e - E1]);
    unsigned m = __match_any_sync(__activemask(), key);
    if ((threadIdx.x & 31) == (__ffs(m) - 1)) atomicAdd(&deg[key], (float)__popc(m));
}

__device__ __forceinline__ unsigned f2tf32(float x) {
    unsigned r;
    asm("cvt.rna.tf32.f32 %0, %1;" : "=r"(r) : "f"(x));
    return r;
}

__device__ __forceinline__ float warp_red(float s) {
#pragma unroll
    for (int off = 16; off; off >>= 1) s += __shfl_xor_sync(0xffffffffu, s, off);
    return s;
}

__device__ __forceinline__ float4 relu4(float4 v) {
    return make_float4(fmaxf(v.x, 0.f), fmaxf(v.y, 0.f), fmaxf(v.z, 0.f), fmaxf(v.w, 0.f));
}

// ---------------- split-TF32 tensor GEMM (templated variants) ----------------
// MODE 0: C = A @ W
// MODE 1: dual — blocks [0,GB): C=A@W ; [GB,2GB): C2=A2@W   (shared W)
// MODE 2: fused h-update: Aupd = (A + g1*relu(agg) + g2*skip)/(1+g1+g2),
//         writes Aupd back to hout (== A buffer) and computes C = Aupd @ W
#define KCH 16
#define SPAD 136
template<int MODE>
__global__ __launch_bounds__(256) void gemm_k(
    const float* A, const float* __restrict__ A2,
    const float* __restrict__ W, float* __restrict__ C, float* __restrict__ C2,
    const float* __restrict__ agg, const float* __restrict__ skip,
    const float* __restrict__ s1, const float* __restrict__ s2,
    const float* __restrict__ deg1, const float* __restrict__ deg2,
    float* hout, int N) {
    __shared__ unsigned As_hi[KCH * SPAD], As_lo[KCH * SPAD];
    __shared__ unsigned Ws_hi[KCH * SPAD], Ws_lo[KCH * SPAD];
    __shared__ float cg1[128], cg2[128], cid[128];

    const int tid = threadIdx.x;
    const int lane = tid & 31;
    const int warp = tid >> 5;
    const int g = lane >> 2;
    const int t = lane & 3;
    const int mbase = warp * 16;

    const float* Ap = A;
    float* Cp = C;
    int rowBase;
    if (MODE == 1) {
        if (blockIdx.x < GB) rowBase = blockIdx.x * 128;
        else { Ap = A2; Cp = C2; rowBase = (blockIdx.x - GB) * 128; }
    } else {
        rowBase = blockIdx.x * 128;
    }

    if (MODE == 2) {
        if (tid < 128) {
            int r = rowBase + tid;
            float g1 = 0.f, g2 = 0.f, invd = 1.f;
            if (r < N) {
                g1 = tanhf(s1[r] / (deg1[r] + 1e-10f));
                g2 = tanhf(s2[r] / (deg2[r] + 1e-10f));
                invd = 1.0f / (1.0f + g1 + g2);
            }
            cg1[tid] = g1; cg2[tid] = g2; cid[tid] = invd;
        }
        __syncthreads();
    }

    float acc[16][4];
#pragma unroll
    for (int n = 0; n < 16; n++)
#pragma unroll
        for (int j = 0; j < 4; j++) acc[n][j] = 0.0f;

    for (int k0 = 0; k0 < HID; k0 += KCH) {
        // A tile: 128 rows x 16 k
#pragma unroll
        for (int tt = 0; tt < 2; tt++) {
            int idx = tid + tt * 256;
            int r = idx >> 2;
            int kq = (idx & 3) * 4;
            float4 v = make_float4(0.f, 0.f, 0.f, 0.f);
            if (rowBase + r < N) {
                size_t off = (size_t)(rowBase + r) * HID + k0 + kq;
                if (MODE == 2) {
                    float4 h4 = *reinterpret_cast<const float4*>(&Ap[off]);
                    float4 a4 = relu4(*reinterpret_cast<const float4*>(&agg[off]));
                    float4 k4 = *reinterpret_cast<const float4*>(&skip[off]);
                    float G1 = cg1[r], G2 = cg2[r], ID = cid[r];
                    v.x = (h4.x + G1 * a4.x + G2 * k4.x) * ID;
                    v.y = (h4.y + G1 * a4.y + G2 * k4.y) * ID;
                    v.z = (h4.z + G1 * a4.z + G2 * k4.z) * ID;
                    v.w = (h4.w + G1 * a4.w + G2 * k4.w) * ID;
                    *reinterpret_cast<float4*>(&hout[off]) = v;
                } else {
                    v = *reinterpret_cast<const float4*>(&Ap[off]);
                }
            }
            float f[4] = {v.x, v.y, v.z, v.w};
#pragma unroll
            for (int j = 0; j < 4; j++) {
                unsigned hi = f2tf32(f[j]);
                float lo = f[j] - __uint_as_float(hi);
                As_hi[(kq + j) * SPAD + r] = hi;
                As_lo[(kq + j) * SPAD + r] = f2tf32(lo);
            }
        }
        // W tile: 16 k-rows x 128 n
#pragma unroll
        for (int tt = 0; tt < 2; tt++) {
            int idx = tid + tt * 256;
            int kr = idx >> 5;
            int nq = (idx & 31) * 4;
            float4 v = *reinterpret_cast<const float4*>(&W[(size_t)(k0 + kr) * HID + nq]);
            float f[4] = {v.x, v.y, v.z, v.w};
#pragma unroll
            for (int j = 0; j < 4; j++) {
                unsigned hi = f2tf32(f[j]);
                float lo = f[j] - __uint_as_float(hi);
                Ws_hi[kr * SPAD + nq + j] = hi;
                Ws_lo[kr * SPAD + nq + j] = f2tf32(lo);
            }
        }
        __syncthreads();

#pragma unroll
        for (int ks = 0; ks < KCH / 8; ks++) {
            int kb = ks * 8;
            unsigned ah[4], al[4];
            ah[0] = As_hi[(kb + t) * SPAD + mbase + g];
            ah[1] = As_hi[(kb + t) * SPAD + mbase + g + 8];
            ah[2] = As_hi[(kb + t + 4) * SPAD + mbase + g];
            ah[3] = As_hi[(kb + t + 4) * SPAD + mbase + g + 8];
            al[0] = As_lo[(kb + t) * SPAD + mbase + g];
            al[1] = As_lo[(kb + t) * SPAD + mbase + g + 8];
            al[2] = As_lo[(kb + t + 4) * SPAD + mbase + g];
            al[3] = As_lo[(kb + t + 4) * SPAD + mbase + g + 8];
#pragma unroll
            for (int nt = 0; nt < 16; nt++) {
                int nb = nt * 8;
                unsigned bh0 = Ws_hi[(kb + t) * SPAD + nb + g];
                unsigned bh1 = Ws_hi[(kb + t + 4) * SPAD + nb + g];
                unsigned bl0 = Ws_lo[(kb + t) * SPAD + nb + g];
                unsigned bl1 = Ws_lo[(kb + t + 4) * SPAD + nb + g];
                asm volatile("mma.sync.aligned.m16n8k8.row.col.f32.tf32.tf32.f32 "
                             "{%0,%1,%2,%3}, {%4,%5,%6,%7}, {%8,%9}, {%0,%1,%2,%3};"
                             : "+f"(acc[nt][0]), "+f"(acc[nt][1]), "+f"(acc[nt][2]), "+f"(acc[nt][3])
                             : "r"(ah[0]), "r"(ah[1]), "r"(ah[2]), "r"(ah[3]), "r"(bh0), "r"(bh1));
                asm volatile("mma.sync.aligned.m16n8k8.row.col.f32.tf32.tf32.f32 "
                             "{%0,%1,%2,%3}, {%4,%5,%6,%7}, {%8,%9}, {%0,%1,%2,%3};"
                             : "+f"(acc[nt][0]), "+f"(acc[nt][1]), "+f"(acc[nt][2]), "+f"(acc[nt][3])
                             : "r"(ah[0]), "r"(ah[1]), "r"(ah[2]), "r"(ah[3]), "r"(bl0), "r"(bl1));
                asm volatile("mma.sync.aligned.m16n8k8.row.col.f32.tf32.tf32.f32 "
                             "{%0,%1,%2,%3}, {%4,%5,%6,%7}, {%8,%9}, {%0,%1,%2,%3};"
                             : "+f"(acc[nt][0]), "+f"(acc[nt][1]), "+f"(acc[nt][2]), "+f"(acc[nt][3])
                             : "r"(al[0]), "r"(al[1]), "r"(al[2]), "r"(al[3]), "r"(bh0), "r"(bh1));
            }
        }
        __syncthreads();
    }

    int r0 = rowBase + mbase + g;
    int r1 = r0 + 8;
    if (r0 < N) {
#pragma unroll
        for (int nt = 0; nt < 16; nt++)
            *reinterpret_cast<float2*>(&Cp[(size_t)r0 * HID + nt * 8 + 2 * t]) =
                make_float2(acc[nt][0], acc[nt][1]);
    }
    if (r1 < N) {
#pragma unroll
        for (int nt = 0; nt < 16; nt++)
            *reinterpret_cast<float2*>(&Cp[(size_t)r1 * HID + nt * 8 + 2 * t]) =
                make_float2(acc[nt][2], acc[nt][3]);
    }
}

// ---------------- scatter: agg[col[e]] += m[row[e]] ----------------
__global__ void scatter_add(const float* __restrict__ m, const int* __restrict__ row,
                            const int* __restrict__ col, float* __restrict__ agg, int E) {
    int w = (blockIdx.x * blockDim.x + threadIdx.x) >> 5;
    if (w >= E) return;
    int lane = threadIdx.x & 31;
    int r = row[w];
    int c = col[w];
    float4 v = *reinterpret_cast<const float4*>(&m[(size_t)r * HID + lane * 4]);
    float* dst = &agg[(size_t)c * HID + lane * 4];
    asm volatile("red.global.add.v4.f32 [%0], {%1, %2, %3, %4};"
                 :: "l"(dst), "f"(v.x), "f"(v.y), "f"(v.z), "f"(v.w) : "memory");
}

// ---------------- fused gamma over both edge lists (relu applied on load) ----------------
#define G2_CHUNK 64
__global__ void gamma_both(const float* __restrict__ agg,
                           const int* __restrict__ row1, const int* __restrict__ col1,
                           float* __restrict__ s1, int E1, int blocks1,
                           const int* __restrict__ row2, const int* __restrict__ col2,
                           float* __restrict__ s2, int E2) {
    int lane = threadIdx.x & 31;
    if (blockIdx.x < blocks1) {
        // 1-hop: warp per edge (rows unsorted)
        int w = (blockIdx.x * blockDim.x + threadIdx.x) >> 5;
        if (w >= E1) return;
        int r = row1[w];
        int c = col1[w];
        float4 a = relu4(*reinterpret_cast<const float4*>(&agg[(size_t)r * HID + lane * 4]));
        float4 b = relu4(*reinterpret_cast<const float4*>(&agg[(size_t)c * HID + lane * 4]));
        float dx = a.x - b.x, dy = a.y - b.y, dz = a.z - b.z, dw = a.w - b.w;
        float s = warp_red(fmaf(dx, dx, fmaf(dy, dy, fmaf(dz, dz, dw * dw))));
        if (lane == 0) atomicAdd(&s1[r], s);
    } else {
        // 2-hop: rows sorted -> warp walks 64-edge chunk caching the row vector
        int w = (int)((((size_t)(blockIdx.x - blocks1) * blockDim.x) + threadIdx.x) >> 5);
        int base = w * G2_CHUNK;
        if (base >= E2) return;
        int end = min(base + G2_CHUNK, E2);
        int curR = row2[base];
        float4 ar = relu4(*reinterpret_cast<const float4*>(&agg[(size_t)curR * HID + lane * 4]));
        float acc = 0.0f;
        for (int e = base; e < end; e++) {
            int r = row2[e];
            if (r != curR) {
                float s = warp_red(acc);
                if (lane == 0) atomicAdd(&s2[curR], s);
                acc = 0.0f;
                curR = r;
                ar = relu4(*reinterpret_cast<const float4*>(&agg[(size_t)r * HID + lane * 4]));
            }
            int c = col2[e];
            float4 ac = relu4(*reinterpret_cast<const float4*>(&agg[(size_t)c * HID + lane * 4]));
            float dx = ar.x - ac.x, dy = ar.y - ac.y, dz = ar.z - ac.z, dw = ar.w - ac.w;
            acc += fmaf(dx, dx, fmaf(dy, dy, fmaf(dz, dz, dw * dw)));
        }
        float s = warp_red(acc);
        if (lane == 0) atomicAdd(&s2[curR], s);
    }
}

// ---------------- final GEMM with fused layer-2 h-update: out = h_upd @ fc_W + fc_b ----------------
#define ORPB 16   // output rows per block
__global__ __launch_bounds__(640) void gemm_out_upd(
    const float* __restrict__ h, const float* __restrict__ agg, const float* __restrict__ skip,
    const float* __restrict__ s1, const float* __restrict__ s2,
    const float* __restrict__ deg1, const float* __restrict__ deg2,
    const float* __restrict__ W, const float* __restrict__ bias,
    float* __restrict__ C, int N) {
    __shared__ float Ws[HID * 41];
    __shared__ float bs[40];
    __shared__ float As[ORPB][HID];
    __shared__ float cg1[ORPB], cg2[ORPB], cid[ORPB];
    int tid = threadIdx.y * 40 + threadIdx.x;   // 640 threads
    int rowBase = blockIdx.x * ORPB;

    for (int i = tid; i < HID * 40; i += 640) {
        int k = i / 40, n = i % 40;
        Ws[k * 41 + n] = W[i];
    }
    if (tid < 40) bs[tid] = bias[tid];
    if (tid < ORPB) {
        int r = rowBase + tid;
        float g1 = 0.f, g2 = 0.f, invd = 1.f;
        if (r < N) {
            g1 = tanhf(s1[r] / (deg1[r] + 1e-10f));
            g2 = tanhf(s2[r] / (deg2[r] + 1e-10f));
            invd = 1.0f / (1.0f + g1 + g2);
        }
        cg1[tid] = g1; cg2[tid] = g2; cid[tid] = invd;
    }
    __syncthreads();

    for (int i = tid; i < ORPB * HID; i += 640) {
        int rr = i >> 7, kk = i & (HID - 1);
        int r = rowBase + rr;
        float v = 0.0f;
        if (r < N) {
            size_t off = (size_t)r * HID + kk;
            v = (h[off] + cg1[rr] * fmaxf(agg[off], 0.f) + cg2[rr] * skip[off]) * cid[rr];
        }
        As[rr][kk] = v;
    }
    __syncthreads();

    int row = rowBase + threadIdx.y;
    if (row >= N) return;
    float acc = bs[threadIdx.x];
#pragma unroll
    for (int k = 0; k < HID; k++) acc = fmaf(As[threadIdx.y][k], Ws[k * 41 + threadIdx.x], acc);
    C[(size_t)row * 40 + threadIdx.x] = acc;
}

// ---------------- launcher ----------------
extern "C" void kernel_launch(void* const* d_in, const int* in_sizes, int n_in,
                              void* d_out, int out_size) {
    const float* x       = (const float*)d_in[0];
    const float* x0      = (const float*)d_in[1];
    const int*   ei      = (const int*)d_in[2];
    const int*   ei2     = (const int*)d_in[3];
    const float* in_W    = (const float*)d_in[4];
    const float* skip_W  = (const float*)d_in[5];
    const float* conv_W  = (const float*)d_in[6];
    const float* conv_b  = (const float*)d_in[7];
    const float* fc_W    = (const float*)d_in[8];
    const float* fc_b    = (const float*)d_in[9];
    float* out = (float*)d_out;

    const int E1 = in_sizes[2] / 2;
    const int E2 = in_sizes[3] / 2;
    const int* row1 = ei;
    const int* col1 = ei + E1;
    const int* row2 = ei2;
    const int* col2 = ei2 + E2;

    float* base;
    cudaGetSymbolAddress((void**)&base, g_scratch);
    float* h    = base + OFF_H;
    float* m    = base + OFF_M;
    float* skip = base + OFF_SKIP;
    float* agg  = base + OFF_AGG;
    float* s1   = base + OFF_S1;
    float* s2   = base + OFF_S2;
    float* deg1 = base + OFF_DEG1;
    float* deg2 = base + OFF_DEG2;

    const int NTH = 256;

    // 1) zero degrees   2) fused degree count
    zero4_kernel<<<(2 * NN / 4 + NTH - 1) / NTH, NTH>>>((float4*)deg1, 2 * NN / 4);
    count_deg_both<<<(E1 + E2 + NTH - 1) / NTH, NTH>>>(row1, E1, row2, E2, deg1);

    // 3) dual input projection: h = x@in_W, m(=h0) = x0@in_W (shared W)
    gemm_k<1><<<2 * GB, NTH>>>(x, x0, in_W, h, m,
                               nullptr, nullptr, nullptr, nullptr, nullptr, nullptr, nullptr, NN);
    // 4) x_skip = h0 @ skip_W
    gemm_k<0><<<GB, NTH>>>(m, nullptr, skip_W, skip, nullptr,
                           nullptr, nullptr, nullptr, nullptr, nullptr, nullptr, nullptr, NN);

    const int initGrid = (NN * HID / 4 + 2 * NN / 4 + NTH - 1) / NTH;
    const int blocks1 = (int)(((size_t)E1 * 32 + NTH - 1) / NTH);
    const int warps2  = (E2 + G2_CHUNK - 1) / G2_CHUNK;
    const int blocks2 = (warps2 * 32 + NTH - 1) / NTH;

    // ---- layer 0 ----
    gemm_k<0><<<GB, NTH>>>(h, nullptr, conv_W, m, nullptr,
                           nullptr, nullptr, nullptr, nullptr, nullptr, nullptr, nullptr, NN);
    init_agg<<<initGrid, NTH>>>((float4*)agg, (const float4*)(conv_b));
    scatter_add<<<(int)(((size_t)E1 * 32 + NTH - 1) / NTH), NTH>>>(m, row1, col1, agg, E1);
    gamma_both<<<blocks1 + blocks2, NTH>>>(agg, row1, col1, s1, E1, blocks1, row2, col2, s2, E2);

    // ---- layer 1 (h-update fused into conv GEMM) ----
    gemm_k<2><<<GB, NTH>>>(h, nullptr, conv_W + (size_t)HID * HID, m, nullptr,
                           agg, skip, s1, s2, deg1, deg2, h, NN);
    init_agg<<<initGrid, NTH>>>((float4*)agg, (const float4*)(conv_b + HID));
    scatter_add<<<(int)(((size_t)E1 * 32 + NTH - 1) / NTH), NTH>>>(m, row1, col1, agg, E1);
    gamma_both<<<blocks1 + blocks2, NTH>>>(agg, row1, col1, s1, E1, blocks1, row2, col2, s2, E2);

    // ---- output (layer-2 h-update fused) ----
    gemm_out_upd<<<(NN + ORPB - 1) / ORPB, dim3(40, ORPB)>>>(
        h, agg, skip, s1, s2, deg1, deg2, fc_W, fc_b, out, NN);
}